// round 5
// baseline (speedup 1.0000x reference)
#include <cuda_runtime.h>

#define N_NODES 50000
#define E_MAX   1600000

// ---------------- scratch (static device globals; no allocation) -------------
__device__ int    g_i64flag;             // 1 if edge_index buffer is int64-laid-out
__device__ int    g_deg[N_NODES];
__device__ float  g_dis[N_NODES];
__device__ int    g_src[E_MAX];
__device__ int    g_dst[E_MAX];
__device__ float4 g_hs  [N_NODES * 16];  // dis[src]-scaled x@W1, 64 f32/node
__device__ float4 g_acc1[N_NODES * 16];  // layer-1 accumulator (init = self msg)
__device__ float4 g_hs2 [N_NODES *  8];  // dis-scaled h@W2, 32 f32/node
__device__ float4 g_acc2[N_NODES *  8];  // layer-2 accumulator

// ---------------- dtype-layout detection --------------------------------------
// int64 layout: odd int32 words are high words == 0 (node ids < 2^31).
// int32 layout: odd words are random node ids; 256 consecutive zeros ~ impossible.
__global__ void k_detect(const int* __restrict__ p) {
    __shared__ int any_nonzero;
    if (threadIdx.x == 0) any_nonzero = 0;
    __syncthreads();
    int v = p[2 * threadIdx.x + 1];          // threads 0..255
    if (v != 0) atomicOr(&any_nonzero, 1);
    __syncthreads();
    if (threadIdx.x == 0) g_i64flag = (any_nonzero == 0) ? 1 : 0;
}

// ---------------- small prep kernels -----------------------------------------
__global__ void k_init_deg() {
    int i = blockIdx.x * blockDim.x + threadIdx.x;
    if (i < N_NODES) g_deg[i] = 1;   // self loop
}

__global__ void k_prep_edges(const int* __restrict__ p, int E) {
    int e = blockIdx.x * blockDim.x + threadIdx.x;
    if (e >= E) return;
    int s, d;
    if (g_i64flag) {                 // int64: low word at even positions
        s = p[2 * e];
        d = p[2 * (E + e)];
    } else {                         // int32: row0 then row1
        s = p[e];
        d = p[E + e];
    }
    // defensive clamp: never let a bad parse produce a wild address
    if ((unsigned)s >= N_NODES) s = 0;
    if ((unsigned)d >= N_NODES) d = 0;
    g_src[e] = s;
    g_dst[e] = d;
    atomicAdd(&g_deg[d], 1);
}

__global__ void k_dis() {
    int i = blockIdx.x * blockDim.x + threadIdx.x;
    if (i < N_NODES) g_dis[i] = rsqrtf((float)g_deg[i]);
}

// ---------------- GEMM1: hs = dis * (x @ W1), also acc1 = hs (self msg) ------
// x:[N,128], W1:[128,64]. Block tile: 64 rows x 64 cols, 128 threads,
// each thread 4 rows x 8 cols (strided mapping for conflict-free smem).
__global__ void k_gemm1(const float* __restrict__ x, const float* __restrict__ W) {
    __shared__ float sWT[64 * 132];   // [col][k], stride 132
    int t = threadIdx.x;              // 0..127
    for (int idx = t; idx < 128 * 64; idx += 128) {
        int k = idx >> 6, c = idx & 63;
        sWT[c * 132 + k] = W[idx];
    }
    __syncthreads();

    int rbase = blockIdx.x * 64 + (t >> 3);  // + 16*i
    int cbase = t & 7;                       // + 8*j
    float acc[4][8];
#pragma unroll
    for (int i = 0; i < 4; i++)
#pragma unroll
        for (int j = 0; j < 8; j++) acc[i][j] = 0.f;

    for (int k = 0; k < 128; k += 4) {
        float4 b[8];
#pragma unroll
        for (int j = 0; j < 8; j++)
            b[j] = *(const float4*)&sWT[(cbase + 8 * j) * 132 + k];
#pragma unroll
        for (int i = 0; i < 4; i++) {
            int r = rbase + 16 * i;
            float4 a = (r < N_NODES) ? *(const float4*)&x[r * 128 + k]
                                     : make_float4(0.f, 0.f, 0.f, 0.f);
#pragma unroll
            for (int j = 0; j < 8; j++) {
                acc[i][j] += a.x * b[j].x;
                acc[i][j] += a.y * b[j].y;
                acc[i][j] += a.z * b[j].z;
                acc[i][j] += a.w * b[j].w;
            }
        }
    }

    float* hs   = (float*)g_hs;
    float* acc1 = (float*)g_acc1;
#pragma unroll
    for (int i = 0; i < 4; i++) {
        int r = rbase + 16 * i;
        if (r < N_NODES) {
            float dv = g_dis[r];
#pragma unroll
            for (int j = 0; j < 8; j++) {
                float v = dv * acc[i][j];
                int o = r * 64 + cbase + 8 * j;
                hs[o]   = v;
                acc1[o] = v;   // self-loop message seeds the accumulator
            }
        }
    }
}

// ---------------- scatter layer 1: acc1[dst] += hs[src] (64 floats) ----------
// One thread per (edge, float4-chunk): vector 16B gather, 4 scalar REDs.
__global__ void k_scatter1(int E) {
    int t = blockIdx.x * blockDim.x + threadIdx.x;
    int e = t >> 4;
    if (e >= E) return;
    int c = t & 15;
    int s = g_src[e];
    int d = g_dst[e];
    float4 v = g_hs[s * 16 + c];
    float* dst = (float*)&g_acc1[d * 16 + c];
    atomicAdd(dst + 0, v.x);
    atomicAdd(dst + 1, v.y);
    atomicAdd(dst + 2, v.z);
    atomicAdd(dst + 3, v.w);
}

// ---------------- h = tanh(dis * acc1), written to d_out h-region ------------
__global__ void k_tanh(float* __restrict__ hout) {
    int idx = blockIdx.x * blockDim.x + threadIdx.x;
    if (idx >= N_NODES * 64) return;
    int row = idx >> 6;
    float v = g_dis[row] * ((const float*)g_acc1)[idx];
    hout[idx] = tanhf(v);
}

// ---------------- GEMM2: hs2 = dis * (h @ W2), acc2 = hs2 --------------------
// h:[N,64], W2:[64,32]. Tile 64 rows x 32 cols, 128 threads, 4 rows x 4 cols.
__global__ void k_gemm2(const float* __restrict__ h, const float* __restrict__ W) {
    __shared__ float sWT[32 * 68];   // [col][k], stride 68
    int t = threadIdx.x;             // 0..127
    for (int idx = t; idx < 64 * 32; idx += 128) {
        int k = idx >> 5, c = idx & 31;
        sWT[c * 68 + k] = W[idx];
    }
    __syncthreads();

    int rbase = blockIdx.x * 64 + (t >> 3);  // + 16*i
    int cbase = t & 7;                       // + 8*j, j<4
    float acc[4][4];
#pragma unroll
    for (int i = 0; i < 4; i++)
#pragma unroll
        for (int j = 0; j < 4; j++) acc[i][j] = 0.f;

    for (int k = 0; k < 64; k += 4) {
        float4 b[4];
#pragma unroll
        for (int j = 0; j < 4; j++)
            b[j] = *(const float4*)&sWT[(cbase + 8 * j) * 68 + k];
#pragma unroll
        for (int i = 0; i < 4; i++) {
            int r = rbase + 16 * i;
            float4 a = (r < N_NODES) ? *(const float4*)&h[r * 64 + k]
                                     : make_float4(0.f, 0.f, 0.f, 0.f);
#pragma unroll
            for (int j = 0; j < 4; j++) {
                acc[i][j] += a.x * b[j].x;
                acc[i][j] += a.y * b[j].y;
                acc[i][j] += a.z * b[j].z;
                acc[i][j] += a.w * b[j].w;
            }
        }
    }

    float* hs2  = (float*)g_hs2;
    float* acc2 = (float*)g_acc2;
#pragma unroll
    for (int i = 0; i < 4; i++) {
        int r = rbase + 16 * i;
        if (r < N_NODES) {
            float dv = g_dis[r];
#pragma unroll
            for (int j = 0; j < 4; j++) {
                float v = dv * acc[i][j];
                int o = r * 32 + cbase + 8 * j;
                hs2[o]  = v;
                acc2[o] = v;
            }
        }
    }
}

// ---------------- scatter layer 2: acc2[dst] += hs2[src] (32 floats) ---------
__global__ void k_scatter2(int E) {
    int t = blockIdx.x * blockDim.x + threadIdx.x;
    int e = t >> 3;
    if (e >= E) return;
    int c = t & 7;
    int s = g_src[e];
    int d = g_dst[e];
    float4 v = g_hs2[s * 8 + c];
    float* dst = (float*)&g_acc2[d * 8 + c];
    atomicAdd(dst + 0, v.x);
    atomicAdd(dst + 1, v.y);
    atomicAdd(dst + 2, v.z);
    atomicAdd(dst + 3, v.w);
}

// ---------------- out = dis * acc2 -------------------------------------------
__global__ void k_out(float* __restrict__ out) {
    int idx = blockIdx.x * blockDim.x + threadIdx.x;
    if (idx >= N_NODES * 32) return;
    int row = idx >> 5;
    out[idx] = g_dis[row] * ((const float*)g_acc2)[idx];
}

// ---------------- launch ------------------------------------------------------
extern "C" void kernel_launch(void* const* d_in, const int* in_sizes, int n_in,
                              void* d_out, int out_size) {
    const float* x  = (const float*)d_in[0];
    const int*   ei = (const int*)d_in[1];     // dtype layout auto-detected
    const float* W1 = (const float*)d_in[2];
    const float* W2 = (const float*)d_in[3];

    float* out  = (float*)d_out;                 // [N,32]
    float* hout = out + N_NODES * 32;            // [N,64]

    int E = in_sizes[1] / 2;                     // 1.6M edges either way
    if (E > E_MAX) E = E_MAX;

    k_detect<<<1, 256>>>(ei);
    k_init_deg<<<(N_NODES + 255) / 256, 256>>>();
    k_prep_edges<<<(E + 255) / 256, 256>>>(ei, E);
    k_dis<<<(N_NODES + 255) / 256, 256>>>();

    k_gemm1<<<(N_NODES + 63) / 64, 128>>>(x, W1);

    long long t1 = (long long)E * 16;
    k_scatter1<<<(unsigned)((t1 + 255) / 256), 256>>>(E);

    k_tanh<<<(N_NODES * 64 + 255) / 256, 256>>>(hout);

    k_gemm2<<<(N_NODES + 63) / 64, 128>>>(hout, W2);

    long long t2 = (long long)E * 8;
    k_scatter2<<<(unsigned)((t2 + 255) / 256), 256>>>(E);

    k_out<<<(N_NODES * 32 + 255) / 256, 256>>>(out);
}

// round 6
// speedup vs baseline: 1.6627x; 1.6627x over previous
#include <cuda_runtime.h>

#define N_NODES 50000
#define E_MAX   1600000

// ---------------- scratch (static device globals; no allocation) -------------
__device__ int    g_i64flag;
__device__ int    g_deg[N_NODES];        // includes self loop
__device__ float  g_dis[N_NODES];
__device__ int    g_src[E_MAX];
__device__ int    g_dst[E_MAX];
__device__ int    g_offs[N_NODES + 1];   // CSR offsets by dst (real edges only)
__device__ int    g_cur[N_NODES];        // bucket cursors
__device__ int    g_csr_src[E_MAX];      // src ids grouped by dst
__device__ float4 g_hs [N_NODES * 16];   // dis[src]-scaled x@W1, 64 f32/node
__device__ float4 g_hs2[N_NODES *  8];   // dis-scaled h@W2, 32 f32/node

// ---------------- dtype-layout detection --------------------------------------
__global__ void k_detect(const int* __restrict__ p) {
    __shared__ int any_nonzero;
    if (threadIdx.x == 0) any_nonzero = 0;
    __syncthreads();
    int v = p[2 * threadIdx.x + 1];
    if (v != 0) atomicOr(&any_nonzero, 1);
    __syncthreads();
    if (threadIdx.x == 0) g_i64flag = (any_nonzero == 0) ? 1 : 0;
}

// ---------------- prep --------------------------------------------------------
__global__ void k_init_deg() {
    int i = blockIdx.x * blockDim.x + threadIdx.x;
    if (i < N_NODES) g_deg[i] = 1;   // self loop
}

__global__ void k_prep_edges(const int* __restrict__ p, int E) {
    int e = blockIdx.x * blockDim.x + threadIdx.x;
    if (e >= E) return;
    int s, d;
    if (g_i64flag) { s = p[2 * e]; d = p[2 * (E + e)]; }
    else           { s = p[e];     d = p[E + e]; }
    if ((unsigned)s >= N_NODES) s = 0;
    if ((unsigned)d >= N_NODES) d = 0;
    g_src[e] = s;
    g_dst[e] = d;
    atomicAdd(&g_deg[d], 1);
}

__global__ void k_dis() {
    int i = blockIdx.x * blockDim.x + threadIdx.x;
    if (i < N_NODES) g_dis[i] = rsqrtf((float)g_deg[i]);
}

// ---------------- exclusive scan of (deg-1) -> offs, cur; single block --------
#define SCAN_T 1024
#define SCAN_CH ((N_NODES + SCAN_T - 1) / SCAN_T)   // 49
__global__ void k_scan() {
    __shared__ int partial[SCAN_T];
    int t = threadIdx.x;
    int base = t * SCAN_CH;
    int sum = 0;
#pragma unroll 4
    for (int i = 0; i < SCAN_CH; i++) {
        int idx = base + i;
        if (idx < N_NODES) sum += g_deg[idx] - 1;
    }
    partial[t] = sum;
    __syncthreads();
    for (int off = 1; off < SCAN_T; off <<= 1) {
        int v = (t >= off) ? partial[t - off] : 0;
        __syncthreads();
        partial[t] += v;
        __syncthreads();
    }
    int run = (t == 0) ? 0 : partial[t - 1];
    for (int i = 0; i < SCAN_CH; i++) {
        int idx = base + i;
        if (idx < N_NODES) {
            g_offs[idx] = run;
            g_cur[idx]  = run;
            run += g_deg[idx] - 1;
        }
    }
    if (t == SCAN_T - 1) g_offs[N_NODES] = partial[SCAN_T - 1];
}

// ---------------- bucket edges by dst ----------------------------------------
__global__ void k_bucket(int E) {
    int e = blockIdx.x * blockDim.x + threadIdx.x;
    if (e >= E) return;
    int d = g_dst[e];
    int pos = atomicAdd(&g_cur[d], 1);
    g_csr_src[pos] = g_src[e];
}

// ---------------- GEMM1: hs = dis * (x @ W1) ---------------------------------
__global__ void k_gemm1(const float* __restrict__ x, const float* __restrict__ W) {
    __shared__ float sWT[64 * 132];
    int t = threadIdx.x;
    for (int idx = t; idx < 128 * 64; idx += 128) {
        int k = idx >> 6, c = idx & 63;
        sWT[c * 132 + k] = W[idx];
    }
    __syncthreads();

    int rbase = blockIdx.x * 64 + (t >> 3);
    int cbase = t & 7;
    float acc[4][8];
#pragma unroll
    for (int i = 0; i < 4; i++)
#pragma unroll
        for (int j = 0; j < 8; j++) acc[i][j] = 0.f;

    for (int k = 0; k < 128; k += 4) {
        float4 b[8];
#pragma unroll
        for (int j = 0; j < 8; j++)
            b[j] = *(const float4*)&sWT[(cbase + 8 * j) * 132 + k];
#pragma unroll
        for (int i = 0; i < 4; i++) {
            int r = rbase + 16 * i;
            float4 a = (r < N_NODES) ? *(const float4*)&x[r * 128 + k]
                                     : make_float4(0.f, 0.f, 0.f, 0.f);
#pragma unroll
            for (int j = 0; j < 8; j++) {
                acc[i][j] += a.x * b[j].x;
                acc[i][j] += a.y * b[j].y;
                acc[i][j] += a.z * b[j].z;
                acc[i][j] += a.w * b[j].w;
            }
        }
    }

    float* hs = (float*)g_hs;
#pragma unroll
    for (int i = 0; i < 4; i++) {
        int r = rbase + 16 * i;
        if (r < N_NODES) {
            float dv = g_dis[r];
#pragma unroll
            for (int j = 0; j < 8; j++)
                hs[r * 64 + cbase + 8 * j] = dv * acc[i][j];
        }
    }
}

// ---------------- gather layer 1 (+tanh fused) -------------------------------
// 64 threads per node (one float each), 4 nodes per 256-thread block.
__global__ void k_gather1(float* __restrict__ hout) {
    int g = blockIdx.x * 4 + (threadIdx.x >> 6);
    if (g >= N_NODES) return;
    int t = threadIdx.x & 63;
    const float* hs = (const float*)g_hs;
    const int* __restrict__ cs = g_csr_src;

    float acc = hs[g * 64 + t];            // self-loop message
    int j   = g_offs[g];
    int end = g_offs[g + 1];
    for (; j + 3 < end; j += 4) {
        int s0 = cs[j], s1 = cs[j + 1], s2 = cs[j + 2], s3 = cs[j + 3];
        float a0 = hs[s0 * 64 + t];
        float a1 = hs[s1 * 64 + t];
        float a2 = hs[s2 * 64 + t];
        float a3 = hs[s3 * 64 + t];
        acc += a0; acc += a1; acc += a2; acc += a3;
    }
    for (; j < end; j++) acc += hs[cs[j] * 64 + t];

    hout[g * 64 + t] = tanhf(g_dis[g] * acc);
}

// ---------------- GEMM2: hs2 = dis * (h @ W2) --------------------------------
__global__ void k_gemm2(const float* __restrict__ h, const float* __restrict__ W) {
    __shared__ float sWT[32 * 68];
    int t = threadIdx.x;
    for (int idx = t; idx < 64 * 32; idx += 128) {
        int k = idx >> 5, c = idx & 31;
        sWT[c * 68 + k] = W[idx];
    }
    __syncthreads();

    int rbase = blockIdx.x * 64 + (t >> 3);
    int cbase = t & 7;
    float acc[4][4];
#pragma unroll
    for (int i = 0; i < 4; i++)
#pragma unroll
        for (int j = 0; j < 4; j++) acc[i][j] = 0.f;

    for (int k = 0; k < 64; k += 4) {
        float4 b[4];
#pragma unroll
        for (int j = 0; j < 4; j++)
            b[j] = *(const float4*)&sWT[(cbase + 8 * j) * 68 + k];
#pragma unroll
        for (int i = 0; i < 4; i++) {
            int r = rbase + 16 * i;
            float4 a = (r < N_NODES) ? *(const float4*)&h[r * 64 + k]
                                     : make_float4(0.f, 0.f, 0.f, 0.f);
#pragma unroll
            for (int j = 0; j < 4; j++) {
                acc[i][j] += a.x * b[j].x;
                acc[i][j] += a.y * b[j].y;
                acc[i][j] += a.z * b[j].z;
                acc[i][j] += a.w * b[j].w;
            }
        }
    }

    float* hs2 = (float*)g_hs2;
#pragma unroll
    for (int i = 0; i < 4; i++) {
        int r = rbase + 16 * i;
        if (r < N_NODES) {
            float dv = g_dis[r];
#pragma unroll
            for (int j = 0; j < 4; j++)
                hs2[r * 32 + cbase + 8 * j] = dv * acc[i][j];
        }
    }
}

// ---------------- gather layer 2 (+final scale fused) ------------------------
// 32 threads per node, 8 nodes per 256-thread block.
__global__ void k_gather2(float* __restrict__ out) {
    int g = blockIdx.x * 8 + (threadIdx.x >> 5);
    if (g >= N_NODES) return;
    int t = threadIdx.x & 31;
    const float* hs2 = (const float*)g_hs2;
    const int* __restrict__ cs = g_csr_src;

    float acc = hs2[g * 32 + t];
    int j   = g_offs[g];
    int end = g_offs[g + 1];
    for (; j + 3 < end; j += 4) {
        int s0 = cs[j], s1 = cs[j + 1], s2 = cs[j + 2], s3 = cs[j + 3];
        float a0 = hs2[s0 * 32 + t];
        float a1 = hs2[s1 * 32 + t];
        float a2 = hs2[s2 * 32 + t];
        float a3 = hs2[s3 * 32 + t];
        acc += a0; acc += a1; acc += a2; acc += a3;
    }
    for (; j < end; j++) acc += hs2[cs[j] * 32 + t];

    out[g * 32 + t] = g_dis[g] * acc;
}

// ---------------- launch ------------------------------------------------------
extern "C" void kernel_launch(void* const* d_in, const int* in_sizes, int n_in,
                              void* d_out, int out_size) {
    const float* x  = (const float*)d_in[0];
    const int*   ei = (const int*)d_in[1];
    const float* W1 = (const float*)d_in[2];
    const float* W2 = (const float*)d_in[3];

    float* out  = (float*)d_out;          // [N,32]
    float* hout = out + N_NODES * 32;     // [N,64]

    int E = in_sizes[1] / 2;
    if (E > E_MAX) E = E_MAX;

    k_detect<<<1, 256>>>(ei);
    k_init_deg<<<(N_NODES + 255) / 256, 256>>>();
    k_prep_edges<<<(E + 255) / 256, 256>>>(ei, E);
    k_dis<<<(N_NODES + 255) / 256, 256>>>();
    k_scan<<<1, SCAN_T>>>();
    k_bucket<<<(E + 255) / 256, 256>>>(E);

    k_gemm1<<<(N_NODES + 63) / 64, 128>>>(x, W1);
    k_gather1<<<(N_NODES + 3) / 4, 256>>>(hout);

    k_gemm2<<<(N_NODES + 63) / 64, 128>>>(hout, W2);
    k_gather2<<<(N_NODES + 7) / 8, 256>>>(out);
}